// round 16
// baseline (speedup 1.0000x reference)
#include <cuda_runtime.h>
#include <cooperative_groups.h>
#include <math.h>

namespace cg = cooperative_groups;

constexpr int BATCH = 32;
constexpr int TLEN  = 2048;
constexpr int DIM   = 256;
constexpr float THRESH = 0.3f;

// Precomputed x-part preactivations: P[t][b][g*256+d], g in {ff1, ff2, tgate}
__device__ float g_P[(size_t)TLEN * BATCH * 768];

// ---------------- packed f32x2 helpers --------------------------------------
__device__ __forceinline__ unsigned long long pk2(float lo, float hi) {
    unsigned long long r;
    asm("mov.b64 %0, {%1, %2};" : "=l"(r) : "f"(lo), "f"(hi));
    return r;
}
__device__ __forceinline__ void upk2(float& lo, float& hi, unsigned long long v) {
    asm("mov.b64 {%0, %1}, %2;" : "=f"(lo), "=f"(hi) : "l"(v));
}
#define FMA2(acc, a, b) asm("fma.rn.f32x2 %0, %1, %2, %0;" : "+l"(acc) : "l"(a), "l"(b))

// ---------------- cluster / mbarrier helpers --------------------------------
__device__ __forceinline__ unsigned smem_u32(const void* p) {
    unsigned a;
    asm("{ .reg .u64 t; cvta.to.shared.u64 t, %1; cvt.u32.u64 %0, t; }" : "=r"(a) : "l"(p));
    return a;
}
__device__ __forceinline__ unsigned mapa_u32(unsigned addr, unsigned rank) {
    unsigned r;
    asm("mapa.shared::cluster.u32 %0, %1, %2;" : "=r"(r) : "r"(addr), "r"(rank));
    return r;
}
__device__ __forceinline__ void mbar_init(unsigned addr, unsigned count) {
    asm volatile("mbarrier.init.shared.b64 [%0], %1;" :: "r"(addr), "r"(count) : "memory");
}
__device__ __forceinline__ void mbar_arrive_expect_tx(unsigned addr, unsigned bytes) {
    asm volatile("mbarrier.arrive.expect_tx.shared.b64 _, [%0], %1;"
                 :: "r"(addr), "r"(bytes) : "memory");
}
// Remote store with transaction-count completion on the REMOTE CTA's mbarrier.
__device__ __forceinline__ void st_async_f32(unsigned rem_addr, float v, unsigned rem_bar) {
    asm volatile("st.async.shared::cluster.mbarrier::complete_tx::bytes.b32 [%0], %1, [%2];"
                 :: "r"(rem_addr), "r"(__float_as_uint(v)), "r"(rem_bar) : "memory");
}
__device__ __forceinline__ void mbar_wait_parity(unsigned addr, unsigned parity) {
    unsigned done;
    asm volatile(
        "{\n\t.reg .pred p;\n\t"
        "mbarrier.try_wait.parity.acquire.cluster.shared::cta.b64 p, [%1], %2;\n\t"
        "selp.b32 %0, 1, 0, p;\n\t}"
        : "=r"(done) : "r"(addr), "r"(parity) : "memory");
    if (!done) {
        asm volatile(
            "{\n\t.reg .pred P1;\n\t"
            "WL_%=:\n\t"
            "mbarrier.try_wait.parity.acquire.cluster.shared::cta.b64 P1, [%0], %1, 0x989680;\n\t"
            "@P1 bra.uni WD_%=;\n\t"
            "bra.uni WL_%=;\n\t"
            "WD_%=:\n\t}"
            :: "r"(addr), "r"(parity) : "memory");
    }
}

// ---------------------------------------------------------------------------
// Phase 1: P = x @ Wx + bias (x-part only, gates {W1, W2, Wta+Wtb}).
// 128x128x16 tile, 256 threads, 8x8 microtile, FFMA2 inner product.
// NEW: register double-buffering — iteration it+1's tiles are LDG'd into
// registers right after the first sync, overlapping the 16-k compute block.
// Same indexing, same k order, same gate-2 add -> P bitwise identical.
// ---------------------------------------------------------------------------
__global__ __launch_bounds__(256) void px_gemm(
    const float* __restrict__ x,
    const float* __restrict__ W1,  const float* __restrict__ b1,
    const float* __restrict__ W2,  const float* __restrict__ b2,
    const float* __restrict__ Wta, const float* __restrict__ bta,
    const float* __restrict__ Wtb, const float* __restrict__ btb)
{
    __shared__ __align__(16) float As[16][132];
    __shared__ __align__(16) float Bs[16][128];

    const int nt    = blockIdx.x;          // 0..5
    const int mt    = blockIdx.y;          // 0..511
    const int gate  = nt >> 1;
    const int ncol0 = (nt & 1) * 128;
    const float* __restrict__ Wg = (gate == 0) ? W1 : (gate == 1) ? W2 : Wta;

    const int tid = threadIdx.x;
    const int tn  = (tid & 15) * 8;
    const int tm  = (tid >> 4) * 8;
    const int m0  = mt * 128;

    // precomputed staging indices (same formulas as before)
    int a_ml[2], a_k4[2], b_kl[2], b_nl4[2];
    size_t a_rowbase[2];
    #pragma unroll
    for (int i = 0; i < 2; i++) {
        int idx = tid + i * 256;
        a_ml[i] = idx >> 2;
        a_k4[i] = (idx & 3) * 4;
        int m = m0 + a_ml[i];
        int b = m & 31;
        int t = m >> 5;
        a_rowbase[i] = ((size_t)b * TLEN + t) * 256;
        b_kl[i]  = idx >> 5;
        b_nl4[i] = (idx & 31) * 4;
    }

    unsigned long long acc2[8][4];
    #pragma unroll
    for (int i = 0; i < 8; i++)
        #pragma unroll
        for (int j = 0; j < 4; j++) acc2[i][j] = 0ull;

    // prefetch tiles for k0 = 0
    float4 a_reg[2], b_reg[2], b2_reg[2];
    #pragma unroll
    for (int i = 0; i < 2; i++) {
        a_reg[i] = *(const float4*)&x[a_rowbase[i] + 0 + a_k4[i]];
        size_t off = (size_t)(0 + b_kl[i]) * 256 + ncol0 + b_nl4[i];
        b_reg[i] = *(const float4*)&Wg[off];
        if (gate == 2) b2_reg[i] = *(const float4*)&Wtb[off];
    }

    for (int it = 0; it < 16; it++) {
        // stage registers -> smem
        #pragma unroll
        for (int i = 0; i < 2; i++) {
            As[a_k4[i] + 0][a_ml[i]] = a_reg[i].x;
            As[a_k4[i] + 1][a_ml[i]] = a_reg[i].y;
            As[a_k4[i] + 2][a_ml[i]] = a_reg[i].z;
            As[a_k4[i] + 3][a_ml[i]] = a_reg[i].w;
            float4 v = b_reg[i];
            if (gate == 2) {
                float4 v2 = b2_reg[i];
                v.x += v2.x; v.y += v2.y; v.z += v2.z; v.w += v2.w;
            }
            *(float4*)&Bs[b_kl[i]][b_nl4[i]] = v;
        }
        __syncthreads();

        // prefetch next iteration's tiles (overlaps the compute below)
        if (it < 15) {
            const int k0n = (it + 1) * 16;
            #pragma unroll
            for (int i = 0; i < 2; i++) {
                a_reg[i] = *(const float4*)&x[a_rowbase[i] + k0n + a_k4[i]];
                size_t off = (size_t)(k0n + b_kl[i]) * 256 + ncol0 + b_nl4[i];
                b_reg[i] = *(const float4*)&Wg[off];
                if (gate == 2) b2_reg[i] = *(const float4*)&Wtb[off];
            }
        }

        #pragma unroll
        for (int k = 0; k < 16; k++) {
            float4 a0 = *(const float4*)&As[k][tm];
            float4 a1 = *(const float4*)&As[k][tm + 4];
            float av[8] = {a0.x, a0.y, a0.z, a0.w, a1.x, a1.y, a1.z, a1.w};
            unsigned long long ap[8];
            #pragma unroll
            for (int i = 0; i < 8; i++) ap[i] = pk2(av[i], av[i]);
            const unsigned long long* bp = (const unsigned long long*)&Bs[k][tn];
            unsigned long long bq0 = bp[0], bq1 = bp[1], bq2 = bp[2], bq3 = bp[3];
            #pragma unroll
            for (int ii = 0; ii < 8; ii++) {
                FMA2(acc2[ii][0], ap[ii], bq0);
                FMA2(acc2[ii][1], ap[ii], bq1);
                FMA2(acc2[ii][2], ap[ii], bq2);
                FMA2(acc2[ii][3], ap[ii], bq3);
            }
        }
        __syncthreads();
    }

    const float* __restrict__ biasA = (gate == 0) ? b1 : (gate == 1) ? b2 : bta;
    float bias[8];
    #pragma unroll
    for (int jj = 0; jj < 8; jj++) {
        float bb = biasA[ncol0 + tn + jj];
        if (gate == 2) bb += btb[ncol0 + tn + jj];
        bias[jj] = bb;
    }
    #pragma unroll
    for (int ii = 0; ii < 8; ii++) {
        float c[8];
        #pragma unroll
        for (int jp = 0; jp < 4; jp++) upk2(c[2*jp], c[2*jp+1], acc2[ii][jp]);
        size_t rowo = (size_t)(m0 + tm + ii) * 768 + (size_t)nt * 128 + tn;
        float4 o0, o1;
        o0.x = c[0] + bias[0]; o0.y = c[1] + bias[1];
        o0.z = c[2] + bias[2]; o0.w = c[3] + bias[3];
        o1.x = c[4] + bias[4]; o1.y = c[5] + bias[5];
        o1.z = c[6] + bias[6]; o1.w = c[7] + bias[7];
        *(float4*)&g_P[rowo]     = o0;
        *(float4*)&g_P[rowo + 4] = o1;
    }
}

// ---------------------------------------------------------------------------
// Phase 2: CfC scan + fused PLIF — R13 VERBATIM (best measured: 3576 us).
// Arrival-driven per-source-rank bars + scalar f32 st.async; float4 psum;
// nl warps at wid 10/11; parity flips only on actual wait.
// ---------------------------------------------------------------------------
__global__ void __launch_bounds__(384, 1) __cluster_dims__(8, 1, 1)
cfc_scan(const float* __restrict__ W1,
         const float* __restrict__ W2,
         const float* __restrict__ Wta,
         const float* __restrict__ Wtb,
         const float* __restrict__ plif_w,
         float* __restrict__ out)
{
    __shared__ __align__(16) float h_sh[2][8][2][32];   // [buf][src_rank][batch][dim32]
    __shared__ __align__(16) float4 ps4[2][96];         // [batch][col] = {q0,q1,q2,q3}
    __shared__ __align__(8)  unsigned long long mbar[2][8];  // [buf][src_rank]

    const unsigned rank = cg::this_cluster().block_rank();
    const int b0  = (blockIdx.x >> 3) * 2;

    const int tid  = threadIdx.x;
    const int q    = tid / 96;
    const int col  = tid % 96;
    const int g    = col >> 5;
    const int j    = col & 31;
    const int d    = (int)rank * 32 + j;
    const int wid  = tid >> 5;
    const int lane = tid & 31;

    const unsigned mb     = smem_u32(mbar);     // bar addr: mb + (buf*8+rank)*8
    const unsigned h_base = smem_u32(h_sh);
    float* const psf = (float*)ps4;             // psf[(nb*96+col)*4 + q]

    // ---- recurrent weights, f32x2 over adjacent k (64 regs) ----
    const float* __restrict__ Wg = (g == 0) ? W1 : (g == 1) ? W2 : Wta;
    unsigned long long wp[32];
    #pragma unroll
    for (int i = 0; i < 32; i++) {
        size_t off0 = (size_t)(256 + q * 64 + 2 * i) * 256 + d;
        float v0 = Wg[off0], v1 = Wg[off0 + 256];
        if (g == 2) { v0 += Wtb[off0]; v1 += Wtb[off0 + 256]; }
        wp[i] = pk2(v0, v1);
    }

    // my two source-rank bars (local) for each buffer
    const unsigned bar_r0_b0 = mb + (unsigned)(0 * 8 + 2 * q) * 8;
    const unsigned bar_r1_b0 = bar_r0_b0 + 8;
    const unsigned bar_r0_b1 = mb + (unsigned)(1 * 8 + 2 * q) * 8;
    const unsigned bar_r1_b1 = bar_r0_b1 + 8;

    // designated armers: tid 96q+64 arms bar[.][2q], tid 96q+65 arms bar[.][2q+1]
    const bool armer0 = (tid == q * 96 + 64);
    const bool armer1 = (tid == q * 96 + 65);

    // nl roles: HIGH-priority warps. warp 10 -> batch b0, warp 11 -> batch b0+1
    const bool is_nl = (wid >= 10);
    const int  nb = wid - 10;
    const int  nd = (int)rank * 32 + lane;
    float decay = 0.f, mem = 0.f;
    unsigned h_rem[8], bar_rem[8];
    if (is_nl) {
        decay = 1.f / (1.f + expf(-plif_w[nd]));
        #pragma unroll
        for (int r = 0; r < 8; r++) {
            h_rem[r]   = mapa_u32(h_base, r);
            bar_rem[r] = mapa_u32(mb, r);
        }
    }

    // init: zero h buffers, init all 16 bars, pre-arm buffer-1 bars (use t=1)
    for (int i = tid; i < 2 * 8 * 2 * 32; i += 384) ((float*)h_sh)[i] = 0.f;
    if (tid == 0) {
        #pragma unroll
        for (int i = 0; i < 16; i++) mbar_init(mb + (unsigned)i * 8, 1);
        #pragma unroll
        for (int r = 0; r < 8; r++) mbar_arrive_expect_tx(mb + (unsigned)(8 + r) * 8, 256);
    }
    __syncthreads();
    cg::this_cluster().sync();    // bars + zeroed h visible cluster-wide

    // prefetch P for t=0
    float px0 = 0.f, px1 = 0.f, px2 = 0.f;
    if (is_nl) {
        const float* pr = g_P + (size_t)(b0 + nb) * 768 + nd;
        px0 = pr[0]; px1 = pr[256]; px2 = pr[512];
    }

    const size_t outB = (size_t)BATCH * TLEN * DIM;
    unsigned p0 = 0, p1 = 0;      // per-buffer wait parities

    for (int t = 0; t < TLEN; t++) {
        const int b = t & 1;
        const unsigned par = b ? p1 : p0;
        const unsigned bar0 = b ? bar_r0_b1 : bar_r0_b0;
        const unsigned bar1 = b ? bar_r1_b1 : bar_r1_b0;

        // prefetch next P
        float pn0 = 0.f, pn1 = 0.f, pn2 = 0.f;
        if (is_nl) {
            int tnx = (t + 1 < TLEN) ? (t + 1) : t;
            const float* pr = g_P + ((size_t)tnx * BATCH + (b0 + nb)) * 768 + nd;
            pn0 = pr[0]; pn1 = pr[256]; pn2 = pr[512];
        }

        // arrival-driven kloop: wait chunk (rank 2q), process; then rank 2q+1.
        unsigned long long accA = 0ull, accB = 0ull;
        if (t > 0) mbar_wait_parity(bar0, par);
        {
            const ulonglong2* a0  = (const ulonglong2*)&h_sh[b][2 * q][0][0];
            const ulonglong2* b0v = (const ulonglong2*)&h_sh[b][2 * q][1][0];
            #pragma unroll
            for (int i2 = 0; i2 < 8; i2++) {
                ulonglong2 ha = a0[i2];
                ulonglong2 hb = b0v[i2];
                FMA2(accA, wp[2 * i2],     ha.x);
                FMA2(accA, wp[2 * i2 + 1], ha.y);
                FMA2(accB, wp[2 * i2],     hb.x);
                FMA2(accB, wp[2 * i2 + 1], hb.y);
            }
        }
        if (t > 0) mbar_wait_parity(bar1, par);
        {
            const ulonglong2* a1  = (const ulonglong2*)&h_sh[b][2 * q + 1][0][0];
            const ulonglong2* b1v = (const ulonglong2*)&h_sh[b][2 * q + 1][1][0];
            #pragma unroll
            for (int i2 = 0; i2 < 8; i2++) {
                ulonglong2 ha = a1[i2];
                ulonglong2 hb = b1v[i2];
                FMA2(accA, wp[16 + 2 * i2], ha.x);
                FMA2(accA, wp[17 + 2 * i2], ha.y);
                FMA2(accB, wp[16 + 2 * i2], hb.x);
                FMA2(accB, wp[17 + 2 * i2], hb.y);
            }
        }
        // parity flip ONLY on an actual wait of this buffer
        if (t > 0) { if (b) p1 ^= 1; else p0 ^= 1; }

        // re-arm this buffer's bars for use at t+2 (ordered before our
        // h(t+1) pushes by the __syncthreads below)
        if (t + 2 < TLEN) {
            if (armer0) mbar_arrive_expect_tx(bar0, 256);
            if (armer1) mbar_arrive_expect_tx(bar1, 256);
        }

        {
            float loA, hiA, loB, hiB;
            upk2(loA, hiA, accA);
            upk2(loB, hiB, accB);
            psf[(0 * 96 + col) * 4 + q] = loA + hiA;
            psf[(1 * 96 + col) * 4 + q] = loB + hiB;
        }
        __syncthreads();

        if (is_nl) {
            // 3 LDS.128: the 4 q-partials per gate, add order == R8
            float4 v0 = ps4[nb][lane];
            float4 v1 = ps4[nb][32 + lane];
            float4 v2 = ps4[nb][64 + lane];
            float s0 = ((v0.x + v0.y) + v0.z) + v0.w + px0;
            float s1 = ((v1.x + v1.y) + v1.z) + v1.w + px1;
            float s2 = ((v2.x + v2.y) + v2.z) + v2.w + px2;
            float ff1 = tanhf(s0);
            float ff2 = tanhf(s1);
            float ti  = 1.f / (1.f + expf(-s2));
            float hn  = ff1 * (1.f - ti) + ti * ff2;

            // push h(t+1): st.async to all 8 ranks; tx on each destination's
            // bar[(t+1)&1][my_rank]
            if (t + 1 < TLEN) {
                const int ub = (t + 1) & 1;
                const unsigned hoff = (unsigned)(((((ub * 8) + (int)rank) * 2 + nb) * 32 + lane) * 4);
                const unsigned boff = (unsigned)((ub * 8 + (int)rank) * 8);
                #pragma unroll
                for (int r = 0; r < 8; r++)
                    st_async_f32(h_rem[r] + hoff, hn, bar_rem[r] + boff);
            }

            // PLIF (forward spk == hard exactly in fp32)
            mem = decay * mem + hn;
            float spk = (mem >= THRESH) ? 1.f : 0.f;
            mem = mem - spk * THRESH;

            size_t o = ((size_t)(b0 + nb) * TLEN + t) * DIM + nd;
            out[o] = hn; out[outB + o] = spk; out[2 * outB + o] = mem;
        }

        px0 = pn0; px1 = pn1; px2 = pn2;
    }

    // exit safety: rendezvous so no CTA exits while its SMEM could still
    // receive straggler traffic.
    cg::this_cluster().sync();
}

// ---------------------------------------------------------------------------
extern "C" void kernel_launch(void* const* d_in, const int* in_sizes, int n_in,
                              void* d_out, int out_size) {
    (void)in_sizes; (void)n_in; (void)out_size;
    const float* x   = (const float*)d_in[0];
    const float* W1  = (const float*)d_in[1];
    const float* b1  = (const float*)d_in[2];
    const float* W2  = (const float*)d_in[3];
    const float* b2  = (const float*)d_in[4];
    const float* Wta = (const float*)d_in[5];
    const float* bta = (const float*)d_in[6];
    const float* Wtb = (const float*)d_in[7];
    const float* btb = (const float*)d_in[8];
    const float* plw = (const float*)d_in[9];
    float* out = (float*)d_out;

    dim3 g1(6, 512);
    px_gemm<<<g1, 256>>>(x, W1, b1, W2, b2, Wta, bta, Wtb, btb);

    cfc_scan<<<128, 384>>>(W1, W2, Wta, Wtb, plw, out);
}

// round 17
// speedup vs baseline: 1.0559x; 1.0559x over previous
#include <cuda_runtime.h>
#include <cooperative_groups.h>
#include <math.h>

namespace cg = cooperative_groups;

constexpr int BATCH = 32;
constexpr int TLEN  = 2048;
constexpr int DIM   = 256;
constexpr float THRESH = 0.3f;

// Precomputed x-part preactivations: P[t][b][g*256+d], g in {ff1, ff2, tgate}
__device__ float g_P[(size_t)TLEN * BATCH * 768];
// Precomputed Wta+Wtb (both halves; gemm uses rows 0..255)
__device__ float g_Wsum[512 * 256];

// ---------------- packed f32x2 helpers --------------------------------------
__device__ __forceinline__ unsigned long long pk2(float lo, float hi) {
    unsigned long long r;
    asm("mov.b64 %0, {%1, %2};" : "=l"(r) : "f"(lo), "f"(hi));
    return r;
}
__device__ __forceinline__ void upk2(float& lo, float& hi, unsigned long long v) {
    asm("mov.b64 {%0, %1}, %2;" : "=f"(lo), "=f"(hi) : "l"(v));
}
#define FMA2(acc, a, b) asm("fma.rn.f32x2 %0, %1, %2, %0;" : "+l"(acc) : "l"(a), "l"(b))

// ---------------- cluster / mbarrier / cp.async helpers ---------------------
__device__ __forceinline__ unsigned smem_u32(const void* p) {
    unsigned a;
    asm("{ .reg .u64 t; cvta.to.shared.u64 t, %1; cvt.u32.u64 %0, t; }" : "=r"(a) : "l"(p));
    return a;
}
__device__ __forceinline__ unsigned mapa_u32(unsigned addr, unsigned rank) {
    unsigned r;
    asm("mapa.shared::cluster.u32 %0, %1, %2;" : "=r"(r) : "r"(addr), "r"(rank));
    return r;
}
__device__ __forceinline__ void mbar_init(unsigned addr, unsigned count) {
    asm volatile("mbarrier.init.shared.b64 [%0], %1;" :: "r"(addr), "r"(count) : "memory");
}
__device__ __forceinline__ void mbar_arrive_expect_tx(unsigned addr, unsigned bytes) {
    asm volatile("mbarrier.arrive.expect_tx.shared.b64 _, [%0], %1;"
                 :: "r"(addr), "r"(bytes) : "memory");
}
__device__ __forceinline__ void st_async_f32(unsigned rem_addr, float v, unsigned rem_bar) {
    asm volatile("st.async.shared::cluster.mbarrier::complete_tx::bytes.b32 [%0], %1, [%2];"
                 :: "r"(rem_addr), "r"(__float_as_uint(v)), "r"(rem_bar) : "memory");
}
__device__ __forceinline__ void mbar_wait_parity(unsigned addr, unsigned parity) {
    unsigned done;
    asm volatile(
        "{\n\t.reg .pred p;\n\t"
        "mbarrier.try_wait.parity.acquire.cluster.shared::cta.b64 p, [%1], %2;\n\t"
        "selp.b32 %0, 1, 0, p;\n\t}"
        : "=r"(done) : "r"(addr), "r"(parity) : "memory");
    if (!done) {
        asm volatile(
            "{\n\t.reg .pred P1;\n\t"
            "WL_%=:\n\t"
            "mbarrier.try_wait.parity.acquire.cluster.shared::cta.b64 P1, [%0], %1, 0x989680;\n\t"
            "@P1 bra.uni WD_%=;\n\t"
            "bra.uni WL_%=;\n\t"
            "WD_%=:\n\t}"
            :: "r"(addr), "r"(parity) : "memory");
    }
}
__device__ __forceinline__ void cp_async16(unsigned smem_addr, const void* gptr) {
    asm volatile("cp.async.cg.shared.global [%0], [%1], 16;"
                 :: "r"(smem_addr), "l"(gptr) : "memory");
}
#define CP_COMMIT() asm volatile("cp.async.commit_group;" ::: "memory")
#define CP_WAIT0()  asm volatile("cp.async.wait_group 0;"  ::: "memory")

// ---------------------------------------------------------------------------
// Prep: g_Wsum = Wta + Wtb (same add the gemm did at staging -> bitwise same)
// ---------------------------------------------------------------------------
__global__ __launch_bounds__(256) void wsum_prep(const float* __restrict__ Wta,
                                                 const float* __restrict__ Wtb) {
    int i = blockIdx.x * 256 + threadIdx.x;
    g_Wsum[i] = Wta[i] + Wtb[i];
}

// ---------------------------------------------------------------------------
// Phase 1: P = x @ Wx + bias. 128x128x16 tile, 256 threads, 8x8 microtile.
// Double-buffered SMEM. B staged by cp.async (zero reg cost, single source
// per gate thanks to g_Wsum); A staged LDG->reg (8 regs)->STS-transpose.
// k order and FMA2 accumulation order unchanged -> P bitwise identical.
// ---------------------------------------------------------------------------
__global__ __launch_bounds__(256, 2) void px_gemm(
    const float* __restrict__ x,
    const float* __restrict__ W1,  const float* __restrict__ b1,
    const float* __restrict__ W2,  const float* __restrict__ b2,
    const float* __restrict__ bta, const float* __restrict__ btb)
{
    __shared__ __align__(16) float As[2][16][132];
    __shared__ __align__(16) float Bs[2][16][128];

    const int nt    = blockIdx.x;          // 0..5
    const int mt    = blockIdx.y;          // 0..511
    const int gate  = nt >> 1;
    const int ncol0 = (nt & 1) * 128;
    const float* __restrict__ Wsrc =
        (gate == 0) ? W1 : (gate == 1) ? W2 : (const float*)g_Wsum;

    const int tid = threadIdx.x;
    const int tn  = (tid & 15) * 8;
    const int tm  = (tid >> 4) * 8;
    const int m0  = mt * 128;

    // staging indices (formulas identical to R13)
    int a_ml[2], a_k4[2], b_kl[2], b_nl4[2];
    size_t a_rowbase[2];
    unsigned bs_dst[2][2];
    #pragma unroll
    for (int i = 0; i < 2; i++) {
        int idx = tid + i * 256;
        a_ml[i] = idx >> 2;
        a_k4[i] = (idx & 3) * 4;
        int m = m0 + a_ml[i];
        int b = m & 31;
        int t = m >> 5;
        a_rowbase[i] = ((size_t)b * TLEN + t) * 256;
        b_kl[i]  = idx >> 5;
        b_nl4[i] = (idx & 31) * 4;
        bs_dst[0][i] = smem_u32(&Bs[0][b_kl[i]][b_nl4[i]]);
        bs_dst[1][i] = smem_u32(&Bs[1][b_kl[i]][b_nl4[i]]);
    }

    unsigned long long acc2[8][4];
    #pragma unroll
    for (int i = 0; i < 8; i++)
        #pragma unroll
        for (int j = 0; j < 4; j++) acc2[i][j] = 0ull;

    // prologue: stage k0=0 into buffer 0
    float4 a_reg[2];
    #pragma unroll
    for (int i = 0; i < 2; i++) {
        a_reg[i] = *(const float4*)&x[a_rowbase[i] + a_k4[i]];
        cp_async16(bs_dst[0][i], &Wsrc[(size_t)b_kl[i] * 256 + ncol0 + b_nl4[i]]);
    }
    CP_COMMIT();
    #pragma unroll
    for (int i = 0; i < 2; i++) {
        As[0][a_k4[i] + 0][a_ml[i]] = a_reg[i].x;
        As[0][a_k4[i] + 1][a_ml[i]] = a_reg[i].y;
        As[0][a_k4[i] + 2][a_ml[i]] = a_reg[i].z;
        As[0][a_k4[i] + 3][a_ml[i]] = a_reg[i].w;
    }
    CP_WAIT0();
    __syncthreads();

    for (int it = 0; it < 16; it++) {
        const int cur = it & 1;
        const int nxt = cur ^ 1;

        // issue next-iteration loads (overlap the compute below)
        if (it < 15) {
            const int k0n = (it + 1) * 16;
            #pragma unroll
            for (int i = 0; i < 2; i++) {
                a_reg[i] = *(const float4*)&x[a_rowbase[i] + k0n + a_k4[i]];
                cp_async16(bs_dst[nxt][i],
                           &Wsrc[(size_t)(k0n + b_kl[i]) * 256 + ncol0 + b_nl4[i]]);
            }
            CP_COMMIT();
        }

        #pragma unroll
        for (int k = 0; k < 16; k++) {
            float4 a0 = *(const float4*)&As[cur][k][tm];
            float4 a1 = *(const float4*)&As[cur][k][tm + 4];
            float av[8] = {a0.x, a0.y, a0.z, a0.w, a1.x, a1.y, a1.z, a1.w};
            unsigned long long ap[8];
            #pragma unroll
            for (int i = 0; i < 8; i++) ap[i] = pk2(av[i], av[i]);
            const unsigned long long* bp = (const unsigned long long*)&Bs[cur][k][tn];
            unsigned long long bq0 = bp[0], bq1 = bp[1], bq2 = bp[2], bq3 = bp[3];
            #pragma unroll
            for (int ii = 0; ii < 8; ii++) {
                FMA2(acc2[ii][0], ap[ii], bq0);
                FMA2(acc2[ii][1], ap[ii], bq1);
                FMA2(acc2[ii][2], ap[ii], bq2);
                FMA2(acc2[ii][3], ap[ii], bq3);
            }
        }

        if (it < 15) {
            #pragma unroll
            for (int i = 0; i < 2; i++) {
                As[nxt][a_k4[i] + 0][a_ml[i]] = a_reg[i].x;
                As[nxt][a_k4[i] + 1][a_ml[i]] = a_reg[i].y;
                As[nxt][a_k4[i] + 2][a_ml[i]] = a_reg[i].z;
                As[nxt][a_k4[i] + 3][a_ml[i]] = a_reg[i].w;
            }
            CP_WAIT0();
        }
        __syncthreads();
    }

    const float* __restrict__ biasA = (gate == 0) ? b1 : (gate == 1) ? b2 : bta;
    float bias[8];
    #pragma unroll
    for (int jj = 0; jj < 8; jj++) {
        float bb = biasA[ncol0 + tn + jj];
        if (gate == 2) bb += btb[ncol0 + tn + jj];
        bias[jj] = bb;
    }
    #pragma unroll
    for (int ii = 0; ii < 8; ii++) {
        float c[8];
        #pragma unroll
        for (int jp = 0; jp < 4; jp++) upk2(c[2*jp], c[2*jp+1], acc2[ii][jp]);
        size_t rowo = (size_t)(m0 + tm + ii) * 768 + (size_t)nt * 128 + tn;
        float4 o0, o1;
        o0.x = c[0] + bias[0]; o0.y = c[1] + bias[1];
        o0.z = c[2] + bias[2]; o0.w = c[3] + bias[3];
        o1.x = c[4] + bias[4]; o1.y = c[5] + bias[5];
        o1.z = c[6] + bias[6]; o1.w = c[7] + bias[7];
        *(float4*)&g_P[rowo]     = o0;
        *(float4*)&g_P[rowo + 4] = o1;
    }
}

// ---------------------------------------------------------------------------
// Phase 2: CfC scan + fused PLIF — R13 VERBATIM (best measured: 3576 us).
// ---------------------------------------------------------------------------
__global__ void __launch_bounds__(384, 1) __cluster_dims__(8, 1, 1)
cfc_scan(const float* __restrict__ W1,
         const float* __restrict__ W2,
         const float* __restrict__ Wta,
         const float* __restrict__ Wtb,
         const float* __restrict__ plif_w,
         float* __restrict__ out)
{
    __shared__ __align__(16) float h_sh[2][8][2][32];   // [buf][src_rank][batch][dim32]
    __shared__ __align__(16) float4 ps4[2][96];         // [batch][col] = {q0,q1,q2,q3}
    __shared__ __align__(8)  unsigned long long mbar[2][8];  // [buf][src_rank]

    const unsigned rank = cg::this_cluster().block_rank();
    const int b0  = (blockIdx.x >> 3) * 2;

    const int tid  = threadIdx.x;
    const int q    = tid / 96;
    const int col  = tid % 96;
    const int g    = col >> 5;
    const int j    = col & 31;
    const int d    = (int)rank * 32 + j;
    const int wid  = tid >> 5;
    const int lane = tid & 31;

    const unsigned mb     = smem_u32(mbar);     // bar addr: mb + (buf*8+rank)*8
    const unsigned h_base = smem_u32(h_sh);
    float* const psf = (float*)ps4;             // psf[(nb*96+col)*4 + q]

    // ---- recurrent weights, f32x2 over adjacent k (64 regs) ----
    const float* __restrict__ Wg = (g == 0) ? W1 : (g == 1) ? W2 : Wta;
    unsigned long long wp[32];
    #pragma unroll
    for (int i = 0; i < 32; i++) {
        size_t off0 = (size_t)(256 + q * 64 + 2 * i) * 256 + d;
        float v0 = Wg[off0], v1 = Wg[off0 + 256];
        if (g == 2) { v0 += Wtb[off0]; v1 += Wtb[off0 + 256]; }
        wp[i] = pk2(v0, v1);
    }

    // my two source-rank bars (local) for each buffer
    const unsigned bar_r0_b0 = mb + (unsigned)(0 * 8 + 2 * q) * 8;
    const unsigned bar_r1_b0 = bar_r0_b0 + 8;
    const unsigned bar_r0_b1 = mb + (unsigned)(1 * 8 + 2 * q) * 8;
    const unsigned bar_r1_b1 = bar_r0_b1 + 8;

    // designated armers: tid 96q+64 arms bar[.][2q], tid 96q+65 arms bar[.][2q+1]
    const bool armer0 = (tid == q * 96 + 64);
    const bool armer1 = (tid == q * 96 + 65);

    // nl roles: HIGH-priority warps. warp 10 -> batch b0, warp 11 -> batch b0+1
    const bool is_nl = (wid >= 10);
    const int  nb = wid - 10;
    const int  nd = (int)rank * 32 + lane;
    float decay = 0.f, mem = 0.f;
    unsigned h_rem[8], bar_rem[8];
    if (is_nl) {
        decay = 1.f / (1.f + expf(-plif_w[nd]));
        #pragma unroll
        for (int r = 0; r < 8; r++) {
            h_rem[r]   = mapa_u32(h_base, r);
            bar_rem[r] = mapa_u32(mb, r);
        }
    }

    // init: zero h buffers, init all 16 bars, pre-arm buffer-1 bars (use t=1)
    for (int i = tid; i < 2 * 8 * 2 * 32; i += 384) ((float*)h_sh)[i] = 0.f;
    if (tid == 0) {
        #pragma unroll
        for (int i = 0; i < 16; i++) mbar_init(mb + (unsigned)i * 8, 1);
        #pragma unroll
        for (int r = 0; r < 8; r++) mbar_arrive_expect_tx(mb + (unsigned)(8 + r) * 8, 256);
    }
    __syncthreads();
    cg::this_cluster().sync();    // bars + zeroed h visible cluster-wide

    // prefetch P for t=0
    float px0 = 0.f, px1 = 0.f, px2 = 0.f;
    if (is_nl) {
        const float* pr = g_P + (size_t)(b0 + nb) * 768 + nd;
        px0 = pr[0]; px1 = pr[256]; px2 = pr[512];
    }

    const size_t outB = (size_t)BATCH * TLEN * DIM;
    unsigned p0 = 0, p1 = 0;      // per-buffer wait parities

    for (int t = 0; t < TLEN; t++) {
        const int b = t & 1;
        const unsigned par = b ? p1 : p0;
        const unsigned bar0 = b ? bar_r0_b1 : bar_r0_b0;
        const unsigned bar1 = b ? bar_r1_b1 : bar_r1_b0;

        // prefetch next P
        float pn0 = 0.f, pn1 = 0.f, pn2 = 0.f;
        if (is_nl) {
            int tnx = (t + 1 < TLEN) ? (t + 1) : t;
            const float* pr = g_P + ((size_t)tnx * BATCH + (b0 + nb)) * 768 + nd;
            pn0 = pr[0]; pn1 = pr[256]; pn2 = pr[512];
        }

        // arrival-driven kloop: wait chunk (rank 2q), process; then rank 2q+1.
        unsigned long long accA = 0ull, accB = 0ull;
        if (t > 0) mbar_wait_parity(bar0, par);
        {
            const ulonglong2* a0  = (const ulonglong2*)&h_sh[b][2 * q][0][0];
            const ulonglong2* b0v = (const ulonglong2*)&h_sh[b][2 * q][1][0];
            #pragma unroll
            for (int i2 = 0; i2 < 8; i2++) {
                ulonglong2 ha = a0[i2];
                ulonglong2 hb = b0v[i2];
                FMA2(accA, wp[2 * i2],     ha.x);
                FMA2(accA, wp[2 * i2 + 1], ha.y);
                FMA2(accB, wp[2 * i2],     hb.x);
                FMA2(accB, wp[2 * i2 + 1], hb.y);
            }
        }
        if (t > 0) mbar_wait_parity(bar1, par);
        {
            const ulonglong2* a1  = (const ulonglong2*)&h_sh[b][2 * q + 1][0][0];
            const ulonglong2* b1v = (const ulonglong2*)&h_sh[b][2 * q + 1][1][0];
            #pragma unroll
            for (int i2 = 0; i2 < 8; i2++) {
                ulonglong2 ha = a1[i2];
                ulonglong2 hb = b1v[i2];
                FMA2(accA, wp[16 + 2 * i2], ha.x);
                FMA2(accA, wp[17 + 2 * i2], ha.y);
                FMA2(accB, wp[16 + 2 * i2], hb.x);
                FMA2(accB, wp[17 + 2 * i2], hb.y);
            }
        }
        // parity flip ONLY on an actual wait of this buffer
        if (t > 0) { if (b) p1 ^= 1; else p0 ^= 1; }

        // re-arm this buffer's bars for use at t+2 (ordered before our
        // h(t+1) pushes by the __syncthreads below)
        if (t + 2 < TLEN) {
            if (armer0) mbar_arrive_expect_tx(bar0, 256);
            if (armer1) mbar_arrive_expect_tx(bar1, 256);
        }

        {
            float loA, hiA, loB, hiB;
            upk2(loA, hiA, accA);
            upk2(loB, hiB, accB);
            psf[(0 * 96 + col) * 4 + q] = loA + hiA;
            psf[(1 * 96 + col) * 4 + q] = loB + hiB;
        }
        __syncthreads();

        if (is_nl) {
            // 3 LDS.128: the 4 q-partials per gate, add order == R8
            float4 v0 = ps4[nb][lane];
            float4 v1 = ps4[nb][32 + lane];
            float4 v2 = ps4[nb][64 + lane];
            float s0 = ((v0.x + v0.y) + v0.z) + v0.w + px0;
            float s1 = ((v1.x + v1.y) + v1.z) + v1.w + px1;
            float s2 = ((v2.x + v2.y) + v2.z) + v2.w + px2;
            float ff1 = tanhf(s0);
            float ff2 = tanhf(s1);
            float ti  = 1.f / (1.f + expf(-s2));
            float hn  = ff1 * (1.f - ti) + ti * ff2;

            // push h(t+1): st.async to all 8 ranks; tx on each destination's
            // bar[(t+1)&1][my_rank]
            if (t + 1 < TLEN) {
                const int ub = (t + 1) & 1;
                const unsigned hoff = (unsigned)(((((ub * 8) + (int)rank) * 2 + nb) * 32 + lane) * 4);
                const unsigned boff = (unsigned)((ub * 8 + (int)rank) * 8);
                #pragma unroll
                for (int r = 0; r < 8; r++)
                    st_async_f32(h_rem[r] + hoff, hn, bar_rem[r] + boff);
            }

            // PLIF (forward spk == hard exactly in fp32)
            mem = decay * mem + hn;
            float spk = (mem >= THRESH) ? 1.f : 0.f;
            mem = mem - spk * THRESH;

            size_t o = ((size_t)(b0 + nb) * TLEN + t) * DIM + nd;
            out[o] = hn; out[outB + o] = spk; out[2 * outB + o] = mem;
        }

        px0 = pn0; px1 = pn1; px2 = pn2;
    }

    // exit safety: rendezvous so no CTA exits while its SMEM could still
    // receive straggler traffic.
    cg::this_cluster().sync();
}

// ---------------------------------------------------------------------------
extern "C" void kernel_launch(void* const* d_in, const int* in_sizes, int n_in,
                              void* d_out, int out_size) {
    (void)in_sizes; (void)n_in; (void)out_size;
    const float* x   = (const float*)d_in[0];
    const float* W1  = (const float*)d_in[1];
    const float* b1  = (const float*)d_in[2];
    const float* W2  = (const float*)d_in[3];
    const float* b2  = (const float*)d_in[4];
    const float* Wta = (const float*)d_in[5];
    const float* bta = (const float*)d_in[6];
    const float* Wtb = (const float*)d_in[7];
    const float* btb = (const float*)d_in[8];
    const float* plw = (const float*)d_in[9];
    float* out = (float*)d_out;

    wsum_prep<<<512, 256>>>(Wta, Wtb);

    dim3 g1(6, 512);
    px_gemm<<<g1, 256>>>(x, W1, b1, W2, b2, bta, btb);

    cfc_scan<<<128, 384>>>(W1, W2, Wta, Wtb, plw, out);
}